// round 11
// baseline (speedup 1.0000x reference)
#include <cuda_runtime.h>
#include <cuda_bf16.h>

// DistortionLoss, O(N log W) hierarchical pairwise merge. One warp per ray,
// 4 elems/lane.
//
// R11: single xor-butterfly ladder replaces scan + reduce. Identity (from the
// R10 quarter decomposition, applied at lane granularity): for two element
// groups A (lower) and B (upper),
//   pair(A∪B) = pair(A) + pair(B) + TW_A*TWS_B - TWS_A*TW_B
// where TW = sum w, TWS = sum w*s, s_k = z_k + z_{k+1}. Each lane computes its
// 4-element intra term + (1/3) w^2 dz term, then 5 butterfly levels carrying
// (T, W, WS) merge lane groups; side sign from the lane bit. All lanes end
// with the ray total. z via aligned-quad loads + neighbor shuffle (R4 path).

#define FULL 0xFFFFFFFFu

__global__ void __launch_bounds__(256) distortion_loss_kernel(
    const float*  __restrict__ w,     // [R,128]
    const float*  __restrict__ z,     // [R,129]
    const float*  __restrict__ nearp, // [R]
    const float*  __restrict__ farp,  // [R]
    float* __restrict__ out)          // [R]
{
    const int ray  = (blockIdx.x * 256 + threadIdx.x) >> 5;
    const int lane = threadIdx.x & 31;

    // ---- aligned-quad z load ----
    const int e0 = ray * 129;          // first element of this row
    const int qa = e0 >> 2;            // first aligned quad overlapping the row
    const int r  = e0 & 3;             // misalignment, uniform across the warp

    const float4* zq = reinterpret_cast<const float4*>(z);
    const float4 q  = zq[qa + lane];   // own aligned quad
    const float4 qx = zq[qa + 32];     // 33rd quad (broadcast, 1 wavefront)

    const float4 w4 = reinterpret_cast<const float4*>(w + (size_t)ray * 128)[lane];
    const float nr  = __ldg(nearp + ray);
    const float fr  = __ldg(farp  + ray);
    const float inv = __fdividef(1.0f, fr - nr);   // off the critical chain

    // ---- reconstruct row elements 4l..4l+4 (warp-uniform branch on r) ----
    float z0, z1, z2, z3, z4;
    const bool last = (lane == 31);
    if (r == 0) {
        z0 = q.x; z1 = q.y; z2 = q.z; z3 = q.w;
        float nx = __shfl_down_sync(FULL, q.x, 1);
        z4 = last ? qx.x : nx;
    } else if (r == 1) {
        z0 = q.y; z1 = q.z; z2 = q.w;
        float nx = __shfl_down_sync(FULL, q.x, 1);
        float ny = __shfl_down_sync(FULL, q.y, 1);
        z3 = last ? qx.x : nx;
        z4 = last ? qx.y : ny;
    } else if (r == 2) {
        z0 = q.z; z1 = q.w;
        float nx = __shfl_down_sync(FULL, q.x, 1);
        float ny = __shfl_down_sync(FULL, q.y, 1);
        float nz = __shfl_down_sync(FULL, q.z, 1);
        z2 = last ? qx.x : nx;
        z3 = last ? qx.y : ny;
        z4 = last ? qx.z : nz;
    } else {
        z0 = q.w;
        float nx = __shfl_down_sync(FULL, q.x, 1);
        float ny = __shfl_down_sync(FULL, q.y, 1);
        float nz = __shfl_down_sync(FULL, q.z, 1);
        float nw = __shfl_down_sync(FULL, q.w, 1);
        z1 = last ? qx.x : nx;
        z2 = last ? qx.y : ny;
        z3 = last ? qx.z : nz;
        z4 = last ? qx.w : nw;
    }

    // ---- lane-local 4-element streaming pass ----
    const float s0 = z0 + z1, s1 = z1 + z2, s2 = z2 + z3, s3 = z3 + z4;
    const float wv0 = w4.x, wv1 = w4.y, wv2 = w4.z, wv3 = w4.w;

    // intra-lane pairwise: T = sum_k w_k*(s_k*W_<k - WS_<k), running W, WS
    const float ws0 = wv0 * s0;
    float T = wv1 * fmaf(s1, wv0, -ws0);                   // k=1 vs k=0
    float W = wv0 + wv1;
    float WS = fmaf(wv1, s1, ws0);
    T = fmaf(wv2, fmaf(s2, W, -WS), T);                    // k=2
    W += wv2;  WS = fmaf(wv2, s2, WS);
    T = fmaf(wv3, fmaf(s3, W, -WS), T);                    // k=3
    W += wv3;  WS = fmaf(wv3, s3, WS);

    // (1/3) w^2 dz term (linear, folded into T before the merge)
    float qq;
    qq  = wv0 * wv0 * (z1 - z0);
    qq += wv1 * wv1 * (z2 - z1);
    qq += wv2 * wv2 * (z3 - z2);
    qq += wv3 * wv3 * (z4 - z3);
    T = fmaf(qq, (1.0f / 3.0f), T);

    // ---- 5-level xor-butterfly merge of (T, W, WS) ----
    #pragma unroll
    for (int off = 1; off < 32; off <<= 1) {
        const float pT  = __shfl_xor_sync(FULL, T,  off);
        const float pW  = __shfl_xor_sync(FULL, W,  off);
        const float pWS = __shfl_xor_sync(FULL, WS, off);
        // cross = TW_A*TWS_B - TWS_A*TW_B ; this lane is side A iff bit off == 0
        const float c   = fmaf(W, pWS, -(WS * pW));
        const float sgn = (lane & off) ? -1.0f : 1.0f;
        T = fmaf(sgn, c, T + pT);
        W  += pW;
        WS += pWS;
    }

    if (lane == 0)
        out[ray] = T * inv;
}

extern "C" void kernel_launch(void* const* d_in, const int* in_sizes, int n_in,
                              void* d_out, int out_size)
{
    const float* w   = (const float*)d_in[0]; // weights [R,128,1]
    const float* z   = (const float*)d_in[1]; // z_vals  [R,129]
    const float* nr  = (const float*)d_in[2]; // near    [R,1]
    const float* fr  = (const float*)d_in[3]; // far     [R,1]
    float*       out = (float*)d_out;         // [R,1]

    const int R = in_sizes[0] / 128;          // 8192
    distortion_loss_kernel<<<R / 8, 256>>>(w, z, nr, fr, out);  // 8 rays / 256-thr CTA
}

// round 12
// speedup vs baseline: 1.0622x; 1.0622x over previous
#include <cuda_runtime.h>
#include <cuda_bf16.h>
#include <cstdint>

// DistortionLoss via warp-private streaming + hierarchical pairwise merge.
//   For an ordered split A|B:  pair(A∪B) = pair(A) + pair(B) + TW_A*TWS_B - TWS_A*TW_B
//   with TW = sum w, TWS = sum w*s, s_k = z_k + z_{k+1}  (raw z-space; near
//   cancels, inv = 1/(far-near) applied once at the end).
//
// R12: each warp owns TWO rays (lanes 0-15 -> ray 2g, 16-31 -> ray 2g+1),
// 8 elements per thread streamed serially in registers (no scan ladders).
// The warp stages its rays' w and z into private smem via cp.async (fully
// coalesced quads), with NO block barriers — commit/wait + __syncwarp only.
// Totals merge in 4 xor-butterfly levels carrying (T, W, WS) per 16-lane half
// (identity validated in R11). ~140 instr/warp vs ~280, at 64% occupancy.

#define FULL 0xFFFFFFFFu

__device__ __forceinline__ void cp_async16(void* smem_dst, const void* gmem_src) {
    uint32_t s = (uint32_t)__cvta_generic_to_shared(smem_dst);
    asm volatile("cp.async.cg.shared.global [%0], [%1], 16;\n" :: "r"(s), "l"(gmem_src));
}

__global__ void __launch_bounds__(256) distortion_loss_kernel(
    const float*  __restrict__ w,     // [R,128]
    const float*  __restrict__ z,     // [R,129]
    const float*  __restrict__ nearp, // [R]
    const float*  __restrict__ farp,  // [R]
    float* __restrict__ out)          // [R]
{
    __shared__ float sm[8][520];      // per-warp slab: w[0..256) + z[256..516)

    const int lane = threadIdx.x & 31;
    const int wc   = threadIdx.x >> 5;            // warp within CTA
    const int gw   = blockIdx.x * 8 + wc;         // global warp id -> rays 2gw, 2gw+1
    const int h    = lane >> 4;                   // which ray (half-warp)
    const int t    = lane & 15;                   // thread within ray

    float* wbuf = sm[wc];
    float* zbuf = sm[wc] + 256;

    // ---- warp-private staging (all quads 16B-aligned, coalesced) ----
    {
        const float4* wsrc = reinterpret_cast<const float4*>(w) + (size_t)gw * 64;
        cp_async16(wbuf + 4 * lane,        wsrc + lane);
        cp_async16(wbuf + 4 * (lane + 32), wsrc + lane + 32);
    }
    const int zf = 258 * gw;                      // first z float of the ray pair
    const int qa = zf >> 2;                       // covering aligned quad
    const int r  = zf & 3;                        // 0 or 2 (uniform per warp)
    {
        const float4* zsrc = reinterpret_cast<const float4*>(z) + qa;
        cp_async16(zbuf + 4 * lane,        zsrc + lane);
        cp_async16(zbuf + 4 * (lane + 32), zsrc + lane + 32);
        if (lane == 0) cp_async16(zbuf + 4 * 64, zsrc + 64);   // 65th quad
    }
    asm volatile("cp.async.commit_group;\n" ::: "memory");

    // overlap: near/far + reciprocal while the copies fly
    const int ray  = 2 * gw + h;
    const float nr = __ldg(nearp + ray);
    const float fr = __ldg(farp  + ray);
    const float inv = __fdividef(1.0f, fr - nr);

    asm volatile("cp.async.wait_group 0;\n" ::: "memory");
    __syncwarp();

    // ---- w: 8 floats (2 aligned quads) at h*128 + 8t ----
    const float4* wv4 = reinterpret_cast<const float4*>(wbuf + h * 128 + 8 * t);
    const float4 wa = wv4[0], wb = wv4[1];

    // ---- z: 12 staged floats covering elements 8t..8t+8 of this ray ----
    const int f0  = r + h * 129 + 8 * t;          // float index in zbuf
    const float4* zb4 = reinterpret_cast<const float4*>(zbuf) + (f0 >> 2);
    const float4 za = zb4[0], zb = zb4[1], zc = zb4[2];
    const int off = f0 & 3;                       // = (r+h)&3, uniform per half

    float zl[9];
    if (off == 0) {
        zl[0]=za.x; zl[1]=za.y; zl[2]=za.z; zl[3]=za.w;
        zl[4]=zb.x; zl[5]=zb.y; zl[6]=zb.z; zl[7]=zb.w; zl[8]=zc.x;
    } else if (off == 1) {
        zl[0]=za.y; zl[1]=za.z; zl[2]=za.w;
        zl[3]=zb.x; zl[4]=zb.y; zl[5]=zb.z; zl[6]=zb.w; zl[7]=zc.x; zl[8]=zc.y;
    } else if (off == 2) {
        zl[0]=za.z; zl[1]=za.w;
        zl[2]=zb.x; zl[3]=zb.y; zl[4]=zb.z; zl[5]=zb.w; zl[6]=zc.x; zl[7]=zc.y; zl[8]=zc.z;
    } else {
        zl[0]=za.w;
        zl[1]=zb.x; zl[2]=zb.y; zl[3]=zb.z; zl[4]=zb.w;
        zl[5]=zc.x; zl[6]=zc.y; zl[7]=zc.z; zl[8]=zc.w;
    }

    const float wl[8] = {wa.x, wa.y, wa.z, wa.w, wb.x, wb.y, wb.z, wb.w};

    // ---- 8-element serial stream: T (pairwise), W, WS, qq (w^2 dz) ----
    float T = 0.f, W = 0.f, WS = 0.f, qq = 0.f;
    #pragma unroll
    for (int k = 0; k < 8; k++) {
        const float wk = wl[k];
        const float s  = zl[k] + zl[k + 1];
        T  = fmaf(wk, fmaf(s, W, -WS), T);        // w_k*(s_k*W_< - WS_<)
        qq = fmaf(wk * wk, zl[k + 1] - zl[k], qq);
        W += wk;
        WS = fmaf(wk, s, WS);
    }
    T = fmaf(qq, (1.0f / 3.0f), T);               // fold linear term (merge-safe)

    // ---- 4-level xor-butterfly merge within the 16-lane half ----
    #pragma unroll
    for (int o = 1; o < 16; o <<= 1) {
        const float pT  = __shfl_xor_sync(FULL, T,  o);
        const float pW  = __shfl_xor_sync(FULL, W,  o);
        const float pWS = __shfl_xor_sync(FULL, WS, o);
        const float c   = fmaf(W, pWS, -(WS * pW));   // TW_me*TWS_peer - TWS_me*TW_peer
        const float sgn = (t & o) ? -1.0f : 1.0f;     // I'm side A (lower) iff bit clear
        T = fmaf(sgn, c, T + pT);
        W  += pW;
        WS += pWS;
    }

    if (t == 0)
        out[ray] = T * inv;
}

extern "C" void kernel_launch(void* const* d_in, const int* in_sizes, int n_in,
                              void* d_out, int out_size)
{
    const float* w   = (const float*)d_in[0]; // weights [R,128,1]
    const float* z   = (const float*)d_in[1]; // z_vals  [R,129]
    const float* nr  = (const float*)d_in[2]; // near    [R,1]
    const float* fr  = (const float*)d_in[3]; // far     [R,1]
    float*       out = (float*)d_out;         // [R,1]

    const int R = in_sizes[0] / 128;          // 8192
    // 2 rays per warp, 8 warps per CTA -> 16 rays per CTA
    distortion_loss_kernel<<<R / 16, 256>>>(w, z, nr, fr, out);
}